// round 2
// baseline (speedup 1.0000x reference)
#include <cuda_runtime.h>
#include <math.h>

#define NUM_TOKENS 16384
#define D_MODEL    2048
#define NUM_EXP    8
#define TOK_PER_WARP 4
#define WARPS_PER_BLOCK 8
#define THREADS (WARPS_PER_BLOCK * 32)
#define TOK_PER_BLOCK (TOK_PER_WARP * WARPS_PER_BLOCK)   // 32
#define D4 (D_MODEL / 4)                                  // 512 float4 per row
#define ITERS (D4 / 32)                                   // 16 iterations per row

extern __shared__ float sW[];   // NUM_EXP * D_MODEL floats = 64 KB

__global__ __launch_bounds__(THREADS, 3)
void gate_kernel(const float* __restrict__ x,
                 const float* __restrict__ W,
                 float* __restrict__ out,
                 int write_experts)
{
    // --- Stage W into shared memory (64 KB), float4 coalesced ---
    const float4* W4 = reinterpret_cast<const float4*>(W);
    float4* sW4 = reinterpret_cast<float4*>(sW);
    #pragma unroll
    for (int i = threadIdx.x; i < NUM_EXP * D4; i += THREADS) {
        sW4[i] = W4[i];
    }
    __syncthreads();

    const int warp = threadIdx.x >> 5;
    const int lane = threadIdx.x & 31;
    const int tok0 = blockIdx.x * TOK_PER_BLOCK + warp * TOK_PER_WARP;

    float acc[NUM_EXP][TOK_PER_WARP];
    #pragma unroll
    for (int e = 0; e < NUM_EXP; e++)
        #pragma unroll
        for (int t = 0; t < TOK_PER_WARP; t++)
            acc[e][t] = 0.0f;

    // Per-token streaming pointers (advance by 32 float4 per iter)
    const float4* xp[TOK_PER_WARP];
    #pragma unroll
    for (int t = 0; t < TOK_PER_WARP; t++)
        xp[t] = reinterpret_cast<const float4*>(x) + (size_t)(tok0 + t) * D4 + lane;

    // --- Double-buffered mainloop: prefetch iter i+1 while computing iter i ---
    float4 buf[2][TOK_PER_WARP];
    #pragma unroll
    for (int t = 0; t < TOK_PER_WARP; t++) {
        buf[0][t] = __ldcs(xp[t]);          // streaming: don't pollute L1
        xp[t] += 32;
    }

    #pragma unroll 2
    for (int it = 0; it < ITERS; it++) {
        const int cur = it & 1;
        if (it + 1 < ITERS) {
            #pragma unroll
            for (int t = 0; t < TOK_PER_WARP; t++) {
                buf[cur ^ 1][t] = __ldcs(xp[t]);
                xp[t] += 32;
            }
        }

        const int col = it * 32 + lane;
        #pragma unroll
        for (int e = 0; e < NUM_EXP; e++) {
            float4 wv = sW4[e * D4 + col];
            #pragma unroll
            for (int t = 0; t < TOK_PER_WARP; t++) {
                float a = acc[e][t];
                a = fmaf(buf[cur][t].x, wv.x, a);
                a = fmaf(buf[cur][t].y, wv.y, a);
                a = fmaf(buf[cur][t].z, wv.z, a);
                a = fmaf(buf[cur][t].w, wv.w, a);
                acc[e][t] = a;
            }
        }
    }

    // --- Warp butterfly reduction: every lane ends with full 8x4 sums ---
    #pragma unroll
    for (int off = 16; off >= 1; off >>= 1) {
        #pragma unroll
        for (int e = 0; e < NUM_EXP; e++)
            #pragma unroll
            for (int t = 0; t < TOK_PER_WARP; t++)
                acc[e][t] += __shfl_xor_sync(0xFFFFFFFFu, acc[e][t], off);
    }

    // Lane l finalizes token l (l < TOK_PER_WARP)
    float logit[NUM_EXP];
    #pragma unroll
    for (int e = 0; e < NUM_EXP; e++) {
        float v = acc[e][0];
        #pragma unroll
        for (int t = 1; t < TOK_PER_WARP; t++)
            v = (lane == t) ? acc[e][t] : v;
        logit[e] = v;
    }

    if (lane < TOK_PER_WARP) {
        const int tok = tok0 + lane;

        // top-2 scan; strict '>' keeps lowest index on ties (JAX top_k order)
        float v1 = logit[0], v2 = -INFINITY;
        int   i1 = 0,        i2 = 0;
        #pragma unroll
        for (int e = 1; e < NUM_EXP; e++) {
            float le = logit[e];
            if (le > v1)      { v2 = v1; i2 = i1; v1 = le; i1 = e; }
            else if (le > v2) { v2 = le; i2 = e; }
        }

        // softmax + top-2 + renormalize collapses to a 2-way softmax
        float r  = __expf(v2 - v1);
        float w1 = 1.0f / (1.0f + r);
        float w2 = 1.0f - w1;

        out[tok * 2 + 0] = w1;
        out[tok * 2 + 1] = w2;
        if (write_experts) {
            out[2 * NUM_TOKENS + tok * 2 + 0] = (float)i1;
            out[2 * NUM_TOKENS + tok * 2 + 1] = (float)i2;
        }
    }
}

extern "C" void kernel_launch(void* const* d_in, const int* in_sizes, int n_in,
                              void* d_out, int out_size)
{
    const float* x = (const float*)d_in[0];
    const float* W = (const float*)d_in[1];
    float* out = (float*)d_out;

    int write_experts = (out_size >= 4 * NUM_TOKENS) ? 1 : 0;

    const int smem = NUM_EXP * D_MODEL * (int)sizeof(float);  // 65536
    cudaFuncSetAttribute(gate_kernel, cudaFuncAttributeMaxDynamicSharedMemorySize, smem);

    gate_kernel<<<NUM_TOKENS / TOK_PER_BLOCK, THREADS, smem>>>(x, W, out, write_experts);
}

// round 3
// speedup vs baseline: 1.1953x; 1.1953x over previous
#include <cuda_runtime.h>
#include <math.h>

#define NUM_TOKENS 16384
#define D_MODEL    2048
#define NUM_EXP    8
#define TOK_PER_GROUP 4
#define NUM_GROUPS (NUM_TOKENS / TOK_PER_GROUP)          // 4096
#define THREADS 512
#define WARPS_PER_BLOCK 16
#define NUM_CTAS 152                                      // GB300: 152 SMs, persistent 1 CTA/SM
#define TOTAL_WARPS (NUM_CTAS * WARPS_PER_BLOCK)          // 2432
#define D4 (D_MODEL / 4)                                  // 512 float4 per row
#define ITERS (D4 / 32)                                   // 16

// Packed fp32x2 FMA (Blackwell sm_103a): d = a*b + d, two fp32 lanes per instr.
__device__ __forceinline__ void fma2(unsigned long long& d,
                                     unsigned long long a,
                                     unsigned long long b)
{
    asm("fma.rn.f32x2 %0, %1, %2, %0;" : "+l"(d) : "l"(a), "l"(b));
}

__device__ __forceinline__ float fold2(unsigned long long v)
{
    float2 f;
    asm("mov.b64 {%0, %1}, %2;" : "=f"(f.x), "=f"(f.y) : "l"(v));
    return f.x + f.y;
}

extern __shared__ float sW[];   // 8 * 2048 floats = 64 KB

__global__ __launch_bounds__(THREADS, 1)
void gate_kernel(const float* __restrict__ x,
                 const float* __restrict__ W,
                 float* __restrict__ out,
                 int write_experts)
{
    // --- Stage W into shared memory (64 KB), float4 coalesced ---
    {
        const float4* W4 = reinterpret_cast<const float4*>(W);
        float4* sW4 = reinterpret_cast<float4*>(sW);
        #pragma unroll
        for (int i = threadIdx.x; i < NUM_EXP * D4; i += THREADS)
            sW4[i] = W4[i];
    }
    __syncthreads();

    const int warp = threadIdx.x >> 5;
    const int lane = threadIdx.x & 31;
    const int gw   = blockIdx.x * WARPS_PER_BLOCK + warp;   // global warp id

    // Balanced static partition of 4096 groups over 2432 warps (1 or 2 each)
    const int gstart = (int)(((long long)gw * NUM_GROUPS) / TOTAL_WARPS);
    const int gend   = (int)(((long long)(gw + 1) * NUM_GROUPS) / TOTAL_WARPS);

    const ulonglong2* xq  = reinterpret_cast<const ulonglong2*>(x);   // float4 as 2x f32x2
    const ulonglong2* sWq = reinterpret_cast<const ulonglong2*>(sW);

    for (int g = gstart; g < gend; g++) {
        const int tok0 = g * TOK_PER_GROUP;
        const ulonglong2* xbase = xq + (size_t)tok0 * D4 + lane;

        // acc[e][t]: one f32x2 per (expert, token) — even/odd component partials
        unsigned long long acc[NUM_EXP][TOK_PER_GROUP];
        #pragma unroll
        for (int e = 0; e < NUM_EXP; e++)
            #pragma unroll
            for (int t = 0; t < TOK_PER_GROUP; t++)
                acc[e][t] = 0ull;

        // Double-buffered x: prefetch next iter's float4s during compute
        ulonglong2 buf[2][TOK_PER_GROUP];
        #pragma unroll
        for (int t = 0; t < TOK_PER_GROUP; t++)
            buf[0][t] = xbase[t * D4];

        #pragma unroll 2
        for (int it = 0; it < ITERS; it++) {
            const int cur = it & 1;
            if (it + 1 < ITERS) {
                #pragma unroll
                for (int t = 0; t < TOK_PER_GROUP; t++)
                    buf[cur ^ 1][t] = xbase[t * D4 + (it + 1) * 32];
            }

            const int col = it * 32 + lane;
            #pragma unroll
            for (int e = 0; e < NUM_EXP; e++) {
                ulonglong2 wv = sWq[e * D4 + col];   // (w0,w1),(w2,w3) packed
                #pragma unroll
                for (int t = 0; t < TOK_PER_GROUP; t++) {
                    fma2(acc[e][t], buf[cur][t].x, wv.x);
                    fma2(acc[e][t], buf[cur][t].y, wv.y);
                }
            }
        }

        // Fold f32x2 halves, then warp butterfly reduction (32 scalars)
        float s[NUM_EXP][TOK_PER_GROUP];
        #pragma unroll
        for (int e = 0; e < NUM_EXP; e++)
            #pragma unroll
            for (int t = 0; t < TOK_PER_GROUP; t++)
                s[e][t] = fold2(acc[e][t]);

        #pragma unroll
        for (int off = 16; off >= 1; off >>= 1)
            #pragma unroll
            for (int e = 0; e < NUM_EXP; e++)
                #pragma unroll
                for (int t = 0; t < TOK_PER_GROUP; t++)
                    s[e][t] += __shfl_xor_sync(0xFFFFFFFFu, s[e][t], off);

        // Lane t (t < 4) finalizes token tok0 + t
        float logit[NUM_EXP];
        #pragma unroll
        for (int e = 0; e < NUM_EXP; e++) {
            float v = s[e][0];
            #pragma unroll
            for (int t = 1; t < TOK_PER_GROUP; t++)
                v = (lane == t) ? s[e][t] : v;
            logit[e] = v;
        }

        if (lane < TOK_PER_GROUP) {
            const int tok = tok0 + lane;

            // top-2 scan; strict '>' keeps lowest index on ties (JAX top_k)
            float v1 = logit[0], v2 = -INFINITY;
            int   i1 = 0,        i2 = 0;
            #pragma unroll
            for (int e = 1; e < NUM_EXP; e++) {
                float le = logit[e];
                if (le > v1)      { v2 = v1; i2 = i1; v1 = le; i1 = e; }
                else if (le > v2) { v2 = le; i2 = e; }
            }

            // softmax + top-2 + renorm == 2-way softmax over top-2 logits
            float r  = __expf(v2 - v1);
            float w1 = 1.0f / (1.0f + r);
            float w2 = 1.0f - w1;

            out[tok * 2 + 0] = w1;
            out[tok * 2 + 1] = w2;
            if (write_experts) {
                out[2 * NUM_TOKENS + tok * 2 + 0] = (float)i1;
                out[2 * NUM_TOKENS + tok * 2 + 1] = (float)i2;
            }
        }
    }
}

extern "C" void kernel_launch(void* const* d_in, const int* in_sizes, int n_in,
                              void* d_out, int out_size)
{
    const float* x = (const float*)d_in[0];
    const float* W = (const float*)d_in[1];
    float* out = (float*)d_out;

    int write_experts = (out_size >= 4 * NUM_TOKENS) ? 1 : 0;

    const int smem = NUM_EXP * D_MODEL * (int)sizeof(float);  // 65536
    cudaFuncSetAttribute(gate_kernel, cudaFuncAttributeMaxDynamicSharedMemorySize, smem);

    gate_kernel<<<NUM_CTAS, THREADS, smem>>>(x, W, out, write_experts);
}